// round 6
// baseline (speedup 1.0000x reference)
#include <cuda_runtime.h>

#define DIM 128
#define NROWS 2048
#define BR 64
#define BC 64
#define CPAD 132     // Cs row stride in floats (odd multiple of 4 -> conflict-free)

typedef unsigned long long ull;

// row-major scratch, d contiguous: g_A[n][d] = hi ; g_C[m][d] = hj + b1
__device__ __align__(128) float g_A[NROWS * DIM];
__device__ __align__(128) float g_C[NROWS * DIM];

// ---------------------------------------------------------------------------
// Precompute: side 0 -> g_A[n][d] = z_i @ W1[:128]
//             side 1 -> g_C[m][d] = z_j @ W1[128:] + b1
// grid (128, 2), block 256: 16 rows x 128 d per block; thread 1 row x 8 d.
// ---------------------------------------------------------------------------
__global__ void precompute_kernel(const float* __restrict__ z_i,
                                  const float* __restrict__ z_j,
                                  const float* __restrict__ W1,
                                  const float* __restrict__ b1) {
    __shared__ __align__(16) float Zs[16][DIM];     // 8KB
    __shared__ __align__(16) float W1s[32][DIM];    // 16KB

    const int side = blockIdx.y;
    const float* z  = side ? z_j : z_i;
    const float* w1 = W1 + side * DIM * DIM;
    const int rowBase = blockIdx.x * 16;
    const int tid = threadIdx.x;

    #pragma unroll
    for (int l = 0; l < 2; l++) {
        int idx = tid + 256 * l;
        int r = idx >> 5, c4 = idx & 31;
        float4 v = ((const float4*)(z + (size_t)(rowBase + r) * DIM))[c4];
        *(float4*)&Zs[r][c4 * 4] = v;
    }

    const int dg = (tid & 15) * 8;
    const int ng = tid >> 4;

    float acc[8];
    #pragma unroll
    for (int j = 0; j < 8; j++) acc[j] = 0.f;

    for (int k0 = 0; k0 < DIM; k0 += 32) {
        __syncthreads();
        #pragma unroll
        for (int l = 0; l < 4; l++) {
            int idx = tid + 256 * l;
            int r = idx >> 5, c4 = idx & 31;
            float4 v = ((const float4*)(w1 + (size_t)(k0 + r) * DIM))[c4];
            *(float4*)&W1s[r][c4 * 4] = v;
        }
        __syncthreads();
        #pragma unroll
        for (int kk = 0; kk < 32; kk++) {
            float4 wa = *(const float4*)&W1s[kk][dg];
            float4 wb = *(const float4*)&W1s[kk][dg + 4];
            float zv = Zs[ng][k0 + kk];
            acc[0] = fmaf(zv, wa.x, acc[0]);
            acc[1] = fmaf(zv, wa.y, acc[1]);
            acc[2] = fmaf(zv, wa.z, acc[2]);
            acc[3] = fmaf(zv, wa.w, acc[3]);
            acc[4] = fmaf(zv, wb.x, acc[4]);
            acc[5] = fmaf(zv, wb.y, acc[5]);
            acc[6] = fmaf(zv, wb.z, acc[6]);
            acc[7] = fmaf(zv, wb.w, acc[7]);
        }
    }

    float o[8];
    #pragma unroll
    for (int j = 0; j < 8; j++)
        o[j] = side ? (acc[j] + b1[dg + j]) : acc[j];
    float* p = (side ? g_C : g_A) + (size_t)(rowBase + ng) * DIM + dg;
    *(float4*)p       = make_float4(o[0], o[1], o[2], o[3]);
    *(float4*)(p + 4) = make_float4(o[4], o[5], o[6], o[7]);
}

// ---------------------------------------------------------------------------
// cp.async helpers
// ---------------------------------------------------------------------------
__device__ __forceinline__ void cpa16(void* smem_dst, const void* gmem_src) {
    unsigned s = (unsigned)__cvta_generic_to_shared(smem_dst);
    asm volatile("cp.async.cg.shared.global [%0], [%1], 16;\n"
                 :: "r"(s), "l"(gmem_src));
}
#define CP_COMMIT() asm volatile("cp.async.commit_group;\n" ::: "memory")
#define CP_WAIT0()  asm volatile("cp.async.wait_group 0;\n" ::: "memory")

// ---------------------------------------------------------------------------
// Main: out[n,m] = sum_d relu(A[n,d] + C[m,d]) * w2[d] + b2
// Full-depth 64x64 tile in smem, loaded ONCE (no chunk loop, 1 barrier).
// Thread: 4 rows x 4 cols, d-pair packed accumulators (16 pairs = 32 regs).
// ---------------------------------------------------------------------------
__global__ void __launch_bounds__(256, 3)
mlp_score_kernel(const float* __restrict__ W2, const float* __restrict__ b2p,
                 float* __restrict__ out) {
    __shared__ __align__(16) float As[BR][DIM];     // 32KB
    __shared__ __align__(16) float Cs[BC][CPAD];    // 33.8KB (only [.][0..127] used)
    __shared__ __align__(16) float Wsm[DIM];        // 0.5KB

    const int tid = threadIdx.x;
    const int tx = tid & 15;        // cols: tx + 16*j, j=0..3
    const int ty = tid >> 4;        // rows: ty*4 + i, i=0..3
    const int rowBase = blockIdx.y * BR;
    const int colBase = blockIdx.x * BC;

    // ---- stage full tiles with cp.async ----
    // As: 64 rows x 32 f4 = 2048 f4; Cs: same count (padded rows)
    {
        const int r = tid >> 2;          // 0..63
        const int f4 = tid & 3;          // 0..3 (x8 slots of stride 4)
        #pragma unroll
        for (int l = 0; l < 8; l++) {
            int c4 = f4 + 4 * l;         // 0..31
            cpa16(&As[r][c4 * 4], &g_A[(size_t)(rowBase + r) * DIM + c4 * 4]);
        }
        #pragma unroll
        for (int l = 0; l < 8; l++) {
            int c4 = f4 + 4 * l;
            cpa16(&Cs[r][c4 * 4], &g_C[(size_t)(colBase + r) * DIM + c4 * 4]);
        }
        if (tid < DIM / 4)
            cpa16(&Wsm[tid * 4], &W2[tid * 4]);
        CP_COMMIT();
    }

    const float b2 = __ldg(b2p);
    const float fz = 0.f;
    ull binit;
    asm("mov.b64 %0, {%1, %2};" : "=l"(binit) : "f"(b2), "f"(fz));

    ull acc[4][4];
    #pragma unroll
    for (int i = 0; i < 4; i++)
        #pragma unroll
        for (int j = 0; j < 4; j++) acc[i][j] = binit;

    CP_WAIT0();
    __syncthreads();   // the ONLY barrier

    #pragma unroll 2
    for (int k = 0; k < DIM / 4; k++) {     // 4 d per step (2 d-pairs)
        ulonglong2 av[4], cv[4];
        #pragma unroll
        for (int i = 0; i < 4; i++)
            av[i] = *(const ulonglong2*)&As[ty * 4 + i][k * 4];
        #pragma unroll
        for (int j = 0; j < 4; j++)
            cv[j] = *(const ulonglong2*)&Cs[tx + 16 * j][k * 4];
        ull w0 = *(const ull*)&Wsm[k * 4];
        ull w1 = *(const ull*)&Wsm[k * 4 + 2];

        #pragma unroll
        for (int i = 0; i < 4; i++) {
            #pragma unroll
            for (int j = 0; j < 4; j++) {
                ull t, r;
                float lo, hi;
                asm("add.rn.f32x2 %0, %1, %2;"
                    : "=l"(t) : "l"(av[i].x), "l"(cv[j].x));
                asm("mov.b64 {%0, %1}, %2;" : "=f"(lo), "=f"(hi) : "l"(t));
                lo = fmaxf(lo, 0.f); hi = fmaxf(hi, 0.f);
                asm("mov.b64 %0, {%1, %2};" : "=l"(r) : "f"(lo), "f"(hi));
                asm("fma.rn.f32x2 %0, %1, %2, %0;"
                    : "+l"(acc[i][j]) : "l"(r), "l"(w0));
                asm("add.rn.f32x2 %0, %1, %2;"
                    : "=l"(t) : "l"(av[i].y), "l"(cv[j].y));
                asm("mov.b64 {%0, %1}, %2;" : "=f"(lo), "=f"(hi) : "l"(t));
                lo = fmaxf(lo, 0.f); hi = fmaxf(hi, 0.f);
                asm("mov.b64 %0, {%1, %2};" : "=l"(r) : "f"(lo), "f"(hi));
                asm("fma.rn.f32x2 %0, %1, %2, %0;"
                    : "+l"(acc[i][j]) : "l"(r), "l"(w1));
            }
        }
    }

    // epilogue: out = acc.lo + acc.hi  (b2 folded into lo at init)
    #pragma unroll
    for (int i = 0; i < 4; i++) {
        const size_t rowOff = (size_t)(rowBase + ty * 4 + i) * NROWS + colBase;
        #pragma unroll
        for (int j = 0; j < 4; j++) {
            float lo, hi;
            asm("mov.b64 {%0, %1}, %2;" : "=f"(lo), "=f"(hi) : "l"(acc[i][j]));
            out[rowOff + tx + 16 * j] = lo + hi;
        }
    }
}

// ---------------------------------------------------------------------------
extern "C" void kernel_launch(void* const* d_in, const int* in_sizes, int n_in,
                              void* d_out, int out_size) {
    (void)in_sizes; (void)n_in; (void)out_size;
    const float* z_i = (const float*)d_in[0];
    const float* z_j = (const float*)d_in[1];
    const float* W1  = (const float*)d_in[2];
    const float* b1  = (const float*)d_in[3];
    const float* W2  = (const float*)d_in[4];
    const float* b2  = (const float*)d_in[5];
    float* out = (float*)d_out;

    precompute_kernel<<<dim3(128, 2), 256>>>(z_i, z_j, W1, b1);
    mlp_score_kernel<<<dim3(NROWS / BC, NROWS / BR), 256>>>(W2, b2, out);
}

// round 7
// speedup vs baseline: 1.0961x; 1.0961x over previous
#include <cuda_runtime.h>

#define DIM 128
#define NROWS 2048
#define BR 64
#define BC 64
#define CPAD 132     // Cs row stride in floats (4 mod 32 -> conflict-free per 8-lane phase)

typedef unsigned long long ull;

// row-major scratch, d contiguous: g_A[n][d] = hi ; g_C[m][d] = hj + b1
__device__ __align__(128) float g_A[NROWS * DIM];
__device__ __align__(128) float g_C[NROWS * DIM];

// ---------------------------------------------------------------------------
// cp.async helpers
// ---------------------------------------------------------------------------
__device__ __forceinline__ void cpa16(void* smem_dst, const void* gmem_src) {
    unsigned s = (unsigned)__cvta_generic_to_shared(smem_dst);
    asm volatile("cp.async.cg.shared.global [%0], [%1], 16;\n"
                 :: "r"(s), "l"(gmem_src));
}
#define CP_COMMIT() asm volatile("cp.async.commit_group;\n" ::: "memory")
#define CP_WAIT0()  asm volatile("cp.async.wait_group 0;\n" ::: "memory")

// ---------------------------------------------------------------------------
// Precompute: side 0 -> g_A[n][d] = z_i @ W1[:128]
//             side 1 -> g_C[m][d] = z_j @ W1[128:] + b1
// grid (64, 2), block 256. Whole W1-half in smem, ONE barrier, then a
// straight 128-deep fma loop. Thread: 2 rows x 8 d (d = dg4..+3, dg4+64..+67).
// ---------------------------------------------------------------------------
__global__ void __launch_bounds__(256, 2)
precompute_kernel(const float* __restrict__ z_i,
                  const float* __restrict__ z_j,
                  const float* __restrict__ W1,
                  const float* __restrict__ b1) {
    __shared__ __align__(16) float Zs[32][DIM];     // 16KB
    __shared__ __align__(16) float W1s[DIM][DIM];   // 64KB

    const int side = blockIdx.y;
    const float* z  = side ? z_j : z_i;
    const float* w1 = W1 + side * DIM * DIM;
    const int rowBase = blockIdx.x * 32;
    const int tid = threadIdx.x;

    // stage Zs (1024 f4) + W1s (4096 f4) with cp.async
    #pragma unroll
    for (int l = 0; l < 4; l++) {
        int idx = tid + 256 * l;
        int r = idx >> 5, c4 = idx & 31;
        cpa16(&Zs[r][c4 * 4], &z[(size_t)(rowBase + r) * DIM + c4 * 4]);
    }
    #pragma unroll
    for (int l = 0; l < 16; l++) {
        int idx = tid + 256 * l;
        int r = idx >> 5, c4 = idx & 31;
        cpa16(&W1s[r][c4 * 4], &w1[(size_t)r * DIM + c4 * 4]);
    }
    CP_COMMIT();
    CP_WAIT0();
    __syncthreads();   // the ONLY barrier

    const int dg4 = (tid & 15) * 4;       // d block 1: dg4..dg4+3 ; block 2: +64
    const int ng  = (tid >> 4) * 2;       // 2 rows

    float acc[2][8];
    #pragma unroll
    for (int i = 0; i < 2; i++)
        #pragma unroll
        for (int j = 0; j < 8; j++) acc[i][j] = 0.f;

    #pragma unroll 4
    for (int k = 0; k < DIM; k++) {
        float4 wa = *(const float4*)&W1s[k][dg4];
        float4 wb = *(const float4*)&W1s[k][dg4 + 64];
        float zv0 = Zs[ng][k];
        float zv1 = Zs[ng + 1][k];
        acc[0][0] = fmaf(zv0, wa.x, acc[0][0]);
        acc[0][1] = fmaf(zv0, wa.y, acc[0][1]);
        acc[0][2] = fmaf(zv0, wa.z, acc[0][2]);
        acc[0][3] = fmaf(zv0, wa.w, acc[0][3]);
        acc[0][4] = fmaf(zv0, wb.x, acc[0][4]);
        acc[0][5] = fmaf(zv0, wb.y, acc[0][5]);
        acc[0][6] = fmaf(zv0, wb.z, acc[0][6]);
        acc[0][7] = fmaf(zv0, wb.w, acc[0][7]);
        acc[1][0] = fmaf(zv1, wa.x, acc[1][0]);
        acc[1][1] = fmaf(zv1, wa.y, acc[1][1]);
        acc[1][2] = fmaf(zv1, wa.z, acc[1][2]);
        acc[1][3] = fmaf(zv1, wa.w, acc[1][3]);
        acc[1][4] = fmaf(zv1, wb.x, acc[1][4]);
        acc[1][5] = fmaf(zv1, wb.y, acc[1][5]);
        acc[1][6] = fmaf(zv1, wb.z, acc[1][6]);
        acc[1][7] = fmaf(zv1, wb.w, acc[1][7]);
    }

    float* dst = side ? g_C : g_A;
    float4 bva = make_float4(0.f, 0.f, 0.f, 0.f);
    float4 bvb = bva;
    if (side) {
        bva = *(const float4*)&b1[dg4];
        bvb = *(const float4*)&b1[dg4 + 64];
    }
    #pragma unroll
    for (int i = 0; i < 2; i++) {
        float* p = &dst[(size_t)(rowBase + ng + i) * DIM];
        *(float4*)(p + dg4) = make_float4(acc[i][0] + bva.x, acc[i][1] + bva.y,
                                          acc[i][2] + bva.z, acc[i][3] + bva.w);
        *(float4*)(p + dg4 + 64) = make_float4(acc[i][4] + bvb.x, acc[i][5] + bvb.y,
                                               acc[i][6] + bvb.z, acc[i][7] + bvb.w);
    }
}

// ---------------------------------------------------------------------------
// Main: out[n,m] = sum_d relu(A[n,d] + C[m,d]) * w2[d] + b2
// Full-depth 64x64 tile in smem, loaded ONCE (no chunk loop, 1 barrier).
// Thread: 4 rows x 4 cols, d-pair packed accumulators (16 pairs = 32 regs).
// ---------------------------------------------------------------------------
__global__ void __launch_bounds__(256, 3)
mlp_score_kernel(const float* __restrict__ W2, const float* __restrict__ b2p,
                 float* __restrict__ out) {
    __shared__ __align__(16) float As[BR][DIM];     // 32KB
    __shared__ __align__(16) float Cs[BC][CPAD];    // 33.8KB
    __shared__ __align__(16) float Wsm[DIM];        // 0.5KB

    const int tid = threadIdx.x;
    const int tx = tid & 15;        // cols: tx + 16*j, j=0..3
    const int ty = tid >> 4;        // rows: ty*4 + i, i=0..3
    const int rowBase = blockIdx.y * BR;
    const int colBase = blockIdx.x * BC;

    // ---- stage full tiles with cp.async ----
    {
        const int r = tid >> 2;          // 0..63
        const int f4 = tid & 3;
        #pragma unroll
        for (int l = 0; l < 8; l++) {
            int c4 = f4 + 4 * l;
            cpa16(&As[r][c4 * 4], &g_A[(size_t)(rowBase + r) * DIM + c4 * 4]);
        }
        #pragma unroll
        for (int l = 0; l < 8; l++) {
            int c4 = f4 + 4 * l;
            cpa16(&Cs[r][c4 * 4], &g_C[(size_t)(colBase + r) * DIM + c4 * 4]);
        }
        if (tid < DIM / 4)
            cpa16(&Wsm[tid * 4], &W2[tid * 4]);
        CP_COMMIT();
    }

    const float b2 = __ldg(b2p);
    const float fz = 0.f;
    ull binit;
    asm("mov.b64 %0, {%1, %2};" : "=l"(binit) : "f"(b2), "f"(fz));

    ull acc[4][4];
    #pragma unroll
    for (int i = 0; i < 4; i++)
        #pragma unroll
        for (int j = 0; j < 4; j++) acc[i][j] = binit;

    CP_WAIT0();
    __syncthreads();   // the ONLY barrier

    #pragma unroll 8
    for (int k = 0; k < DIM / 4; k++) {     // 4 d per step (2 d-pairs)
        ulonglong2 av[4], cv[4];
        #pragma unroll
        for (int i = 0; i < 4; i++)
            av[i] = *(const ulonglong2*)&As[ty * 4 + i][k * 4];
        #pragma unroll
        for (int j = 0; j < 4; j++)
            cv[j] = *(const ulonglong2*)&Cs[tx + 16 * j][k * 4];
        ull w0 = *(const ull*)&Wsm[k * 4];
        ull w1 = *(const ull*)&Wsm[k * 4 + 2];

        #pragma unroll
        for (int i = 0; i < 4; i++) {
            #pragma unroll
            for (int j = 0; j < 4; j++) {
                ull t, r;
                float lo, hi;
                asm("add.rn.f32x2 %0, %1, %2;"
                    : "=l"(t) : "l"(av[i].x), "l"(cv[j].x));
                asm("mov.b64 {%0, %1}, %2;" : "=f"(lo), "=f"(hi) : "l"(t));
                lo = fmaxf(lo, 0.f); hi = fmaxf(hi, 0.f);
                asm("mov.b64 %0, {%1, %2};" : "=l"(r) : "f"(lo), "f"(hi));
                asm("fma.rn.f32x2 %0, %1, %2, %0;"
                    : "+l"(acc[i][j]) : "l"(r), "l"(w0));
                asm("add.rn.f32x2 %0, %1, %2;"
                    : "=l"(t) : "l"(av[i].y), "l"(cv[j].y));
                asm("mov.b64 {%0, %1}, %2;" : "=f"(lo), "=f"(hi) : "l"(t));
                lo = fmaxf(lo, 0.f); hi = fmaxf(hi, 0.f);
                asm("mov.b64 %0, {%1, %2};" : "=l"(r) : "f"(lo), "f"(hi));
                asm("fma.rn.f32x2 %0, %1, %2, %0;"
                    : "+l"(acc[i][j]) : "l"(r), "l"(w1));
            }
        }
    }

    // epilogue: out = acc.lo + acc.hi  (b2 folded into lo at init)
    #pragma unroll
    for (int i = 0; i < 4; i++) {
        const size_t rowOff = (size_t)(rowBase + ty * 4 + i) * NROWS + colBase;
        #pragma unroll
        for (int j = 0; j < 4; j++) {
            float lo, hi;
            asm("mov.b64 {%0, %1}, %2;" : "=f"(lo), "=f"(hi) : "l"(acc[i][j]));
            out[rowOff + tx + 16 * j] = lo + hi;
        }
    }
}

// ---------------------------------------------------------------------------
extern "C" void kernel_launch(void* const* d_in, const int* in_sizes, int n_in,
                              void* d_out, int out_size) {
    (void)in_sizes; (void)n_in; (void)out_size;
    const float* z_i = (const float*)d_in[0];
    const float* z_j = (const float*)d_in[1];
    const float* W1  = (const float*)d_in[2];
    const float* b1  = (const float*)d_in[3];
    const float* W2  = (const float*)d_in[4];
    const float* b2  = (const float*)d_in[5];
    float* out = (float*)d_out;

    precompute_kernel<<<dim3(64, 2), 256>>>(z_i, z_j, W1, b1);
    mlp_score_kernel<<<dim3(NROWS / BC, NROWS / BR), 256>>>(W2, b2, out);
}

// round 8
// speedup vs baseline: 1.2625x; 1.1518x over previous
#include <cuda_runtime.h>

#define DIM 128
#define NROWS 2048
#define BR 64
#define BC 64
#define CPAD 132     // Cs row stride in floats -> conflict-free strided col reads

typedef unsigned long long ull;

// row-major scratch, d contiguous: g_A[n][d] = hi ; g_C[m][d] = hj + b1
__device__ __align__(128) float g_A[NROWS * DIM];
__device__ __align__(128) float g_C[NROWS * DIM];

// ---------------------------------------------------------------------------
// cp.async helpers
// ---------------------------------------------------------------------------
__device__ __forceinline__ void cpa16(void* smem_dst, const void* gmem_src) {
    unsigned s = (unsigned)__cvta_generic_to_shared(smem_dst);
    asm volatile("cp.async.cg.shared.global [%0], [%1], 16;\n"
                 :: "r"(s), "l"(gmem_src));
}
#define CP_COMMIT() asm volatile("cp.async.commit_group;\n" ::: "memory")
#define CP_WAIT0()  asm volatile("cp.async.wait_group 0;\n" ::: "memory")

// ---------------------------------------------------------------------------
// Precompute: side 0 -> g_A[n][d] = z_i @ W1[:128]
//             side 1 -> g_C[m][d] = z_j @ W1[128:] + b1
// grid (64, 2), block 256. Whole W1-half in smem, ONE barrier, then a
// straight 128-deep fma loop. Thread: 2 rows x 8 d.
// ---------------------------------------------------------------------------
__global__ void __launch_bounds__(256, 2)
precompute_kernel(const float* __restrict__ z_i,
                  const float* __restrict__ z_j,
                  const float* __restrict__ W1,
                  const float* __restrict__ b1) {
    __shared__ __align__(16) float Zs[32][DIM];     // 16KB
    __shared__ __align__(16) float W1s[DIM][DIM];   // 64KB

    const int side = blockIdx.y;
    const float* z  = side ? z_j : z_i;
    const float* w1 = W1 + side * DIM * DIM;
    const int rowBase = blockIdx.x * 32;
    const int tid = threadIdx.x;

    #pragma unroll
    for (int l = 0; l < 4; l++) {
        int idx = tid + 256 * l;
        int r = idx >> 5, c4 = idx & 31;
        cpa16(&Zs[r][c4 * 4], &z[(size_t)(rowBase + r) * DIM + c4 * 4]);
    }
    #pragma unroll
    for (int l = 0; l < 16; l++) {
        int idx = tid + 256 * l;
        int r = idx >> 5, c4 = idx & 31;
        cpa16(&W1s[r][c4 * 4], &w1[(size_t)r * DIM + c4 * 4]);
    }
    CP_COMMIT();
    CP_WAIT0();
    __syncthreads();   // the ONLY barrier

    const int dg4 = (tid & 15) * 4;
    const int ng  = (tid >> 4) * 2;

    float acc[2][8];
    #pragma unroll
    for (int i = 0; i < 2; i++)
        #pragma unroll
        for (int j = 0; j < 8; j++) acc[i][j] = 0.f;

    #pragma unroll 4
    for (int k = 0; k < DIM; k++) {
        float4 wa = *(const float4*)&W1s[k][dg4];
        float4 wb = *(const float4*)&W1s[k][dg4 + 64];
        float zv0 = Zs[ng][k];
        float zv1 = Zs[ng + 1][k];
        acc[0][0] = fmaf(zv0, wa.x, acc[0][0]);
        acc[0][1] = fmaf(zv0, wa.y, acc[0][1]);
        acc[0][2] = fmaf(zv0, wa.z, acc[0][2]);
        acc[0][3] = fmaf(zv0, wa.w, acc[0][3]);
        acc[0][4] = fmaf(zv0, wb.x, acc[0][4]);
        acc[0][5] = fmaf(zv0, wb.y, acc[0][5]);
        acc[0][6] = fmaf(zv0, wb.z, acc[0][6]);
        acc[0][7] = fmaf(zv0, wb.w, acc[0][7]);
        acc[1][0] = fmaf(zv1, wa.x, acc[1][0]);
        acc[1][1] = fmaf(zv1, wa.y, acc[1][1]);
        acc[1][2] = fmaf(zv1, wa.z, acc[1][2]);
        acc[1][3] = fmaf(zv1, wa.w, acc[1][3]);
        acc[1][4] = fmaf(zv1, wb.x, acc[1][4]);
        acc[1][5] = fmaf(zv1, wb.y, acc[1][5]);
        acc[1][6] = fmaf(zv1, wb.z, acc[1][6]);
        acc[1][7] = fmaf(zv1, wb.w, acc[1][7]);
    }

    float* dst = side ? g_C : g_A;
    float4 bva = make_float4(0.f, 0.f, 0.f, 0.f);
    float4 bvb = bva;
    if (side) {
        bva = *(const float4*)&b1[dg4];
        bvb = *(const float4*)&b1[dg4 + 64];
    }
    #pragma unroll
    for (int i = 0; i < 2; i++) {
        float* p = &dst[(size_t)(rowBase + ng + i) * DIM];
        *(float4*)(p + dg4) = make_float4(acc[i][0] + bva.x, acc[i][1] + bva.y,
                                          acc[i][2] + bva.z, acc[i][3] + bva.w);
        *(float4*)(p + dg4 + 64) = make_float4(acc[i][4] + bvb.x, acc[i][5] + bvb.y,
                                               acc[i][6] + bvb.z, acc[i][7] + bvb.w);
    }
}

// ---------------------------------------------------------------------------
// Main: out[n,m] = sum_d relu(A[n,d] + C[m,d]) * w2[d] + b2
// Full-depth 64x64 tile in smem, loaded ONCE (no chunk loop, 1 barrier).
// Thread: 4 rows x 4 cols, d-pair packed accumulators (16 pairs = 32 regs).
// Unroll 2 (body fits L0 I$ — unroll 8 regressed, R7).
// ---------------------------------------------------------------------------
__global__ void __launch_bounds__(256, 3)
mlp_score_kernel(const float* __restrict__ W2, const float* __restrict__ b2p,
                 float* __restrict__ out) {
    __shared__ __align__(16) float As[BR][DIM];     // 32KB
    __shared__ __align__(16) float Cs[BC][CPAD];    // 33.8KB
    __shared__ __align__(16) float Wsm[DIM];        // 0.5KB

    const int tid = threadIdx.x;
    const int tx = tid & 15;        // cols: tx + 16*j, j=0..3
    const int ty = tid >> 4;        // rows: ty*4 + i, i=0..3
    const int rowBase = blockIdx.y * BR;
    const int colBase = blockIdx.x * BC;

    // ---- stage full tiles with cp.async ----
    {
        const int r = tid >> 2;          // 0..63
        const int f4 = tid & 3;
        #pragma unroll
        for (int l = 0; l < 8; l++) {
            int c4 = f4 + 4 * l;
            cpa16(&As[r][c4 * 4], &g_A[(size_t)(rowBase + r) * DIM + c4 * 4]);
        }
        #pragma unroll
        for (int l = 0; l < 8; l++) {
            int c4 = f4 + 4 * l;
            cpa16(&Cs[r][c4 * 4], &g_C[(size_t)(colBase + r) * DIM + c4 * 4]);
        }
        if (tid < DIM / 4)
            cpa16(&Wsm[tid * 4], &W2[tid * 4]);
        CP_COMMIT();
    }

    const float b2 = __ldg(b2p);
    const float fz = 0.f;
    ull binit;
    asm("mov.b64 %0, {%1, %2};" : "=l"(binit) : "f"(b2), "f"(fz));

    ull acc[4][4];
    #pragma unroll
    for (int i = 0; i < 4; i++)
        #pragma unroll
        for (int j = 0; j < 4; j++) acc[i][j] = binit;

    CP_WAIT0();
    __syncthreads();   // the ONLY barrier

    #pragma unroll 2
    for (int k = 0; k < DIM / 4; k++) {     // 4 d per step (2 d-pairs)
        ulonglong2 av[4], cv[4];
        #pragma unroll
        for (int i = 0; i < 4; i++)
            av[i] = *(const ulonglong2*)&As[ty * 4 + i][k * 4];
        #pragma unroll
        for (int j = 0; j < 4; j++)
            cv[j] = *(const ulonglong2*)&Cs[tx + 16 * j][k * 4];
        ull w0 = *(const ull*)&Wsm[k * 4];
        ull w1 = *(const ull*)&Wsm[k * 4 + 2];

        #pragma unroll
        for (int i = 0; i < 4; i++) {
            #pragma unroll
            for (int j = 0; j < 4; j++) {
                ull t, r;
                float lo, hi;
                asm("add.rn.f32x2 %0, %1, %2;"
                    : "=l"(t) : "l"(av[i].x), "l"(cv[j].x));
                asm("mov.b64 {%0, %1}, %2;" : "=f"(lo), "=f"(hi) : "l"(t));
                lo = fmaxf(lo, 0.f); hi = fmaxf(hi, 0.f);
                asm("mov.b64 %0, {%1, %2};" : "=l"(r) : "f"(lo), "f"(hi));
                asm("fma.rn.f32x2 %0, %1, %2, %0;"
                    : "+l"(acc[i][j]) : "l"(r), "l"(w0));
                asm("add.rn.f32x2 %0, %1, %2;"
                    : "=l"(t) : "l"(av[i].y), "l"(cv[j].y));
                asm("mov.b64 {%0, %1}, %2;" : "=f"(lo), "=f"(hi) : "l"(t));
                lo = fmaxf(lo, 0.f); hi = fmaxf(hi, 0.f);
                asm("mov.b64 %0, {%1, %2};" : "=l"(r) : "f"(lo), "f"(hi));
                asm("fma.rn.f32x2 %0, %1, %2, %0;"
                    : "+l"(acc[i][j]) : "l"(r), "l"(w1));
            }
        }
    }

    // epilogue: out = acc.lo + acc.hi  (b2 folded into lo at init)
    #pragma unroll
    for (int i = 0; i < 4; i++) {
        const size_t rowOff = (size_t)(rowBase + ty * 4 + i) * NROWS + colBase;
        #pragma unroll
        for (int j = 0; j < 4; j++) {
            float lo, hi;
            asm("mov.b64 {%0, %1}, %2;" : "=f"(lo), "=f"(hi) : "l"(acc[i][j]));
            out[rowOff + tx + 16 * j] = lo + hi;
        }
    }
}

// ---------------------------------------------------------------------------
extern "C" void kernel_launch(void* const* d_in, const int* in_sizes, int n_in,
                              void* d_out, int out_size) {
    (void)in_sizes; (void)n_in; (void)out_size;
    const float* z_i = (const float*)d_in[0];
    const float* z_j = (const float*)d_in[1];
    const float* W1  = (const float*)d_in[2];
    const float* b1  = (const float*)d_in[3];
    const float* W2  = (const float*)d_in[4];
    const float* b2  = (const float*)d_in[5];
    float* out = (float*)d_out;

    precompute_kernel<<<dim3(64, 2), 256>>>(z_i, z_j, W1, b1);
    mlp_score_kernel<<<dim3(NROWS / BC, NROWS / BR), 256>>>(W2, b2, out);
}